// round 1
// baseline (speedup 1.0000x reference)
#include <cuda_runtime.h>
#include <cstdint>

// GptOssExperts: out[t,h] = sum_e r[t,e] * ( act( hs @ gup[e] + gub[e] ) @ dp[e] + dpb[e] )
// Folding r into the intermediate activation turns stage 2 into ONE big GEMM over K = E*I.

constexpr int T_DIM   = 2048;
constexpr int H_DIM   = 2048;
constexpr int I_DIM   = 2048;
constexpr int E_NUM   = 8;
constexpr int GU_COLS = 2 * I_DIM;       // 4096
constexpr int KQ      = E_NUM * I_DIM;   // 16384

constexpr int BM = 128, BN = 128, BK = 16;
constexpr int SSTR = 136;                // padded smem row stride (conflict-free frags)

// scratch: routed-scaled intermediate activations, layout [T, E*I]
__device__ float g_inter[33554432];      // 2048 * 16384 floats = 134 MB

__device__ __forceinline__ uint32_t f2tf32(float x) {
    uint32_t r;
    asm("cvt.rna.tf32.f32 %0, %1;" : "=r"(r) : "f"(x));
    return r;
}

__device__ __forceinline__ void mma_tf32(float (&c)[4],
    uint32_t a0, uint32_t a1, uint32_t a2, uint32_t a3,
    uint32_t b0, uint32_t b1)
{
    asm volatile(
        "mma.sync.aligned.m16n8k8.row.col.f32.tf32.tf32.f32 "
        "{%0,%1,%2,%3}, {%4,%5,%6,%7}, {%8,%9}, {%0,%1,%2,%3};"
        : "+f"(c[0]), "+f"(c[1]), "+f"(c[2]), "+f"(c[3])
        : "r"(a0), "r"(a1), "r"(a2), "r"(a3), "r"(b0), "r"(b1));
}

// ---- tile store: global-staged regs -> smem (with tf32 conversion) ----
__device__ __forceinline__ void store_tiles(
    uint32_t (&As)[BK][SSTR], uint32_t (&Bs)[BK][SSTR],
    const float4& va0, const float4& va1,
    const float4& vb0, const float4& vb1,
    int am0, int ak0, int bk0, int bn0)
{
    // A stored transposed: As[k][m]
    As[ak0 + 0][am0] = f2tf32(va0.x);
    As[ak0 + 1][am0] = f2tf32(va0.y);
    As[ak0 + 2][am0] = f2tf32(va0.z);
    As[ak0 + 3][am0] = f2tf32(va0.w);
    const int am1 = am0 + 64;
    As[ak0 + 0][am1] = f2tf32(va1.x);
    As[ak0 + 1][am1] = f2tf32(va1.y);
    As[ak0 + 2][am1] = f2tf32(va1.z);
    As[ak0 + 3][am1] = f2tf32(va1.w);
    // B stored natural: Bs[k][n], vectorized 16B store
    uint4 p;
    p.x = f2tf32(vb0.x); p.y = f2tf32(vb0.y); p.z = f2tf32(vb0.z); p.w = f2tf32(vb0.w);
    *reinterpret_cast<uint4*>(&Bs[bk0][bn0]) = p;
    p.x = f2tf32(vb1.x); p.y = f2tf32(vb1.y); p.z = f2tf32(vb1.z); p.w = f2tf32(vb1.w);
    *reinterpret_cast<uint4*>(&Bs[bk0 + 8][bn0]) = p;
}

// ---- compute one BK=16 slab (two k=8 substeps) from a smem buffer ----
__device__ __forceinline__ void compute_tile(
    const uint32_t (&As)[BK][SSTR], const uint32_t (&Bs)[BK][SSTR],
    int wm, int wn, int g, int t4, float (&acc)[2][8][4])
{
#pragma unroll
    for (int ks = 0; ks < BK; ks += 8) {
        uint32_t af0[4], af1[4];
        {
            const int m = wm * 32 + g;
            af0[0] = As[ks + t4][m];          af0[1] = As[ks + t4][m + 8];
            af0[2] = As[ks + t4 + 4][m];      af0[3] = As[ks + t4 + 4][m + 8];
            af1[0] = As[ks + t4][m + 16];     af1[1] = As[ks + t4][m + 24];
            af1[2] = As[ks + t4 + 4][m + 16]; af1[3] = As[ks + t4 + 4][m + 24];
        }
#pragma unroll
        for (int nt = 0; nt < 8; nt++) {
            const int n = wn * 64 + nt * 8 + g;
            const uint32_t b0 = Bs[ks + t4][n];
            const uint32_t b1 = Bs[ks + t4 + 4][n];
            mma_tf32(acc[0][nt], af0[0], af0[1], af0[2], af0[3], b0, b1);
            mma_tf32(acc[1][nt], af1[0], af1[1], af1[2], af1[3], b0, b1);
        }
    }
}

// ---- main loop: double-buffered smem, one __syncthreads per BK slab ----
__device__ __forceinline__ void gemm_tiles(
    const float* __restrict__ A, int lda,
    const float* __restrict__ B, int ldb,
    int K,
    uint32_t (*As)[BK][SSTR], uint32_t (*Bs)[BK][SSTR],
    float (&acc)[2][8][4])
{
    const int tid  = threadIdx.x;
    const int lane = tid & 31;
    const int w    = tid >> 5;
    const int wm = w >> 1, wn = w & 1;
    const int g = lane >> 2, t4 = lane & 3;

    const int am0 = tid >> 2, ak0 = (tid & 3) << 2;
    const int am1 = am0 + 64;
    const int bk0 = tid >> 5, bn0 = (tid & 31) << 2;
    const int bk1 = bk0 + 8;

    const float* Ap0 = A + (size_t)am0 * lda + ak0;
    const float* Ap1 = A + (size_t)am1 * lda + ak0;
    const float* Bp0 = B + (size_t)bk0 * ldb + bn0;
    const float* Bp1 = B + (size_t)bk1 * ldb + bn0;

    float4 va0 = *(const float4*)Ap0;
    float4 va1 = *(const float4*)Ap1;
    float4 vb0 = *(const float4*)Bp0;
    float4 vb1 = *(const float4*)Bp1;

    store_tiles(As[0], Bs[0], va0, va1, vb0, vb1, am0, ak0, bk0, bn0);
    __syncthreads();

    int buf = 0;
    for (int k0 = BK; k0 < K; k0 += BK) {
        va0 = *(const float4*)(Ap0 + k0);
        va1 = *(const float4*)(Ap1 + k0);
        vb0 = *(const float4*)(Bp0 + (size_t)k0 * ldb);
        vb1 = *(const float4*)(Bp1 + (size_t)k0 * ldb);
        compute_tile(As[buf], Bs[buf], wm, wn, g, t4, acc);
        store_tiles(As[buf ^ 1], Bs[buf ^ 1], va0, va1, vb0, vb1, am0, ak0, bk0, bn0);
        __syncthreads();
        buf ^= 1;
    }
    compute_tile(As[buf], Bs[buf], wm, wn, g, t4, acc);
}

// ================= Stage 1: gu = hs @ gup[e] + gub[e]; GLU; scale by routing =================
__global__ __launch_bounds__(256) void k_gemm1(
    const float* __restrict__ hidden,
    const float* __restrict__ routing,
    const float* __restrict__ gup,
    const float* __restrict__ gub)
{
    __shared__ __align__(16) uint32_t As[2][BK][SSTR];
    __shared__ __align__(16) uint32_t Bs[2][BK][SSTR];
    __shared__ float rs[BM];
    __shared__ float bsm[BN];

    const int e  = blockIdx.z;
    const int t0 = blockIdx.y * BM;
    const int j0 = blockIdx.x * BN;   // gu-column base (covers 64 inter columns)
    const int tid = threadIdx.x;

    if (tid < BM) rs[tid] = routing[(size_t)(t0 + tid) * E_NUM + e];
    else          bsm[tid - BM] = gub[(size_t)e * GU_COLS + j0 + (tid - BM)];

    float acc[2][8][4] = {};
    gemm_tiles(hidden + (size_t)t0 * H_DIM, H_DIM,
               gup + (size_t)e * H_DIM * GU_COLS + j0, GU_COLS,
               H_DIM, As, Bs, acc);

    const int lane = tid & 31, w = tid >> 5;
    const int wm = w >> 1, wn = w & 1, g = lane >> 2, t4 = lane & 3;
#pragma unroll
    for (int mt = 0; mt < 2; mt++) {
#pragma unroll
        for (int nt = 0; nt < 8; nt++) {
            const int cl = wn * 64 + nt * 8 + 2 * t4;  // even gu col (gate); cl+1 = up
#pragma unroll
            for (int h = 0; h < 2; h++) {
                const int r = wm * 32 + mt * 16 + g + h * 8;
                float gate = acc[mt][nt][2 * h]     + bsm[cl];
                float up   = acc[mt][nt][2 * h + 1] + bsm[cl + 1];
                gate = fminf(gate, 7.0f);
                up   = fminf(fmaxf(up, -7.0f), 7.0f);
                const float glu = gate / (1.0f + __expf(-1.702f * gate));
                const float val = (up + 1.0f) * glu * rs[r];
                g_inter[(size_t)(t0 + r) * KQ + (size_t)e * I_DIM + ((j0 + cl) >> 1)] = val;
            }
        }
    }
}

// ================= Stage 2: out = inter'[T, E*I] @ down[E*I, H] + routing @ dpb =================
__global__ __launch_bounds__(256) void k_gemm2(
    const float* __restrict__ routing,
    const float* __restrict__ down,
    const float* __restrict__ dpb,
    float* __restrict__ out)
{
    __shared__ __align__(16) uint32_t As[2][BK][SSTR];
    __shared__ __align__(16) uint32_t Bs[2][BK][SSTR];
    __shared__ float rsm[BM][E_NUM];
    __shared__ float dsm[E_NUM][BN];

    const int t0 = blockIdx.y * BM;
    const int h0 = blockIdx.x * BN;
    const int tid = threadIdx.x;

    for (int i = tid; i < BM * E_NUM; i += 256)
        rsm[i >> 3][i & 7] = routing[(size_t)(t0 + (i >> 3)) * E_NUM + (i & 7)];
    for (int i = tid; i < E_NUM * BN; i += 256)
        dsm[i >> 7][i & 127] = dpb[(size_t)(i >> 7) * H_DIM + h0 + (i & 127)];

    float acc[2][8][4] = {};
    gemm_tiles(g_inter + (size_t)t0 * KQ, KQ,
               down + h0, H_DIM,
               KQ, As, Bs, acc);

    const int lane = tid & 31, w = tid >> 5;
    const int wm = w >> 1, wn = w & 1, g = lane >> 2, t4 = lane & 3;
#pragma unroll
    for (int mt = 0; mt < 2; mt++) {
#pragma unroll
        for (int nt = 0; nt < 8; nt++) {
            const int cl = wn * 64 + nt * 8 + 2 * t4;
#pragma unroll
            for (int h = 0; h < 2; h++) {
                const int r = wm * 32 + mt * 16 + g + h * 8;
                float b0 = 0.0f, b1 = 0.0f;
#pragma unroll
                for (int e = 0; e < E_NUM; e++) {
                    const float rw = rsm[r][e];
                    b0 += rw * dsm[e][cl];
                    b1 += rw * dsm[e][cl + 1];
                }
                const size_t o = (size_t)(t0 + r) * H_DIM + h0;
                out[o + cl]     = acc[mt][nt][2 * h]     + b0;
                out[o + cl + 1] = acc[mt][nt][2 * h + 1] + b1;
            }
        }
    }
}

extern "C" void kernel_launch(void* const* d_in, const int* in_sizes, int n_in,
                              void* d_out, int out_size)
{
    const float* hidden  = (const float*)d_in[0];
    const float* routing = (const float*)d_in[1];
    const float* gup     = (const float*)d_in[2];
    const float* gub     = (const float*)d_in[3];
    const float* down    = (const float*)d_in[4];
    const float* dpb     = (const float*)d_in[5];
    float* out = (float*)d_out;

    dim3 g1(GU_COLS / BN, T_DIM / BM, E_NUM);   // (32, 16, 8)
    k_gemm1<<<g1, 256>>>(hidden, routing, gup, gub);

    dim3 g2(H_DIM / BN, T_DIM / BM);            // (16, 16)
    k_gemm2<<<g2, 256>>>(routing, down, dpb, out);
}